// round 9
// baseline (speedup 1.0000x reference)
#include <cuda_runtime.h>
#include <cuda_fp16.h>
#include <math.h>
#include <stdint.h>

#define N_NODES 50000
#define N_EDGES 800000
#define N_GRAPHS 512
#define D_IN 128
#define D_EDGE 32
#define D_HID 128
#define D_GLOB 64
#define K1 288

#define TILE_M 64                  /* node kernel tile */
#define TILE_E 128                 /* edge kernel tile */
#define NT2 (N_EDGES / TILE_E)     /* 6250 tiles */
#define EDGE_GRID 148
#define ETHREADS 256               /* 8 warps: 4 wm x 2 wn, 32x64 warp tiles */

#define A_STRIDE 296               /* halves: 592 B rows */
#define H_STRIDE 136               /* halves: 272 B rows */
#define STG_STRIDE 68              /* f32:    272 B rows */

// ---- scratch ----
__device__ float  g_agg[N_NODES * D_HID];
__device__ float  g_pooled[N_GRAPHS * D_HID];
__device__ float  g_counts[N_GRAPHS];
__device__ __half g_xh[N_NODES * D_IN];
__device__ __half g_eah[N_EDGES * D_EDGE];
// fp16 weight images: byte(k,n) = k*256 + (((n>>3)^(k&7))*16) + (n&7)*2
__device__ __half g_B1h[K1 * D_HID];
__device__ __half g_B2h[D_HID * D_HID];
__device__ __half g_Bgh[2 * D_HID * D_HID];
__device__ __half g_Bnh[2 * D_HID * D_HID];

// ---- edge kernel SMEM layout (bytes) ----
#define E_IDX   0                          /* 2 bufs x 256 ints = 2048 */
#define E_BE1   2048
#define E_BE2   2560
#define E_A     3072                       /* 128 x 592 = 75776 */
#define E_H     (E_A + 75776)              /* 78848: 128 x 272 = 34816 */
#define E_W1    (E_H + 34816)              /* 113664: 73728 */
#define E_W2    (E_W1 + 73728)             /* 187392: 32768 */
#define E_TOTAL (E_W2 + 32768)             /* 220160 */

// ---- node kernel SMEM layout ----
#define N_BG    0
#define N_BN    512
#define N_A     1024
#define N_W     (N_A + 37888)
#define N_TOTAL (N_W + 65536)

// ============================ PTX helpers ===================================
__device__ __forceinline__ uint32_t smem_u32(const void* p) {
    uint32_t a;
    asm("{ .reg .u64 t; cvta.to.shared.u64 t, %1; cvt.u32.u64 %0, t; }" : "=r"(a) : "l"(p));
    return a;
}
__device__ __forceinline__ void ldm_x4(uint32_t* r, uint32_t addr) {
    asm volatile("ldmatrix.sync.aligned.m8n8.x4.shared.b16 {%0,%1,%2,%3}, [%4];"
                 : "=r"(r[0]), "=r"(r[1]), "=r"(r[2]), "=r"(r[3]) : "r"(addr));
}
__device__ __forceinline__ void ldm_x4_t(uint32_t* r, uint32_t addr) {
    asm volatile("ldmatrix.sync.aligned.m8n8.x4.trans.shared.b16 {%0,%1,%2,%3}, [%4];"
                 : "=r"(r[0]), "=r"(r[1]), "=r"(r[2]), "=r"(r[3]) : "r"(addr));
}
__device__ __forceinline__ void mma16816(float* c, const uint32_t* a, uint32_t b0, uint32_t b1) {
    asm volatile(
        "mma.sync.aligned.m16n8k16.row.col.f32.f16.f16.f32 "
        "{%0,%1,%2,%3}, {%4,%5,%6,%7}, {%8,%9}, {%0,%1,%2,%3};"
        : "+f"(c[0]), "+f"(c[1]), "+f"(c[2]), "+f"(c[3])
        : "r"(a[0]), "r"(a[1]), "r"(a[2]), "r"(a[3]), "r"(b0), "r"(b1));
}
__device__ __forceinline__ void red_add_v4(float* p, float a, float b, float c, float d) {
    asm volatile("red.global.add.v4.f32 [%0], {%1, %2, %3, %4};"
                 :: "l"(p), "f"(a), "f"(b), "f"(c), "f"(d) : "memory");
}
__device__ __forceinline__ void red_add_v2(float* p, float a, float b) {
    asm volatile("red.global.add.v2.f32 [%0], {%1, %2};" :: "l"(p), "f"(a), "f"(b) : "memory");
}
__device__ __forceinline__ void cpa16(uint32_t dst, const void* src) {
    asm volatile("cp.async.cg.shared.global [%0], [%1], 16;" :: "r"(dst), "l"(src) : "memory");
}
#define CPA_COMMIT() asm volatile("cp.async.commit_group;" ::: "memory")
#define CPA_WAIT0()  asm volatile("cp.async.wait_group 0;" ::: "memory")
__device__ __forceinline__ uint32_t h2_bits(__half2 h) {
    return *reinterpret_cast<uint32_t*>(&h);
}

// ============================================================================
__global__ void zero_kernel() {
    int idx = blockIdx.x * blockDim.x + threadIdx.x;
    int stride = gridDim.x * blockDim.x;
    float4 z = make_float4(0.f, 0.f, 0.f, 0.f);
    float4* a4 = (float4*)g_agg;
    for (int i = idx; i < N_NODES * D_HID / 4; i += stride) a4[i] = z;
    for (int i = idx; i < N_GRAPHS * D_HID; i += stride) g_pooled[i] = 0.0f;
    for (int i = idx; i < N_GRAPHS; i += stride) g_counts[i] = 0.0f;
}

__global__ void prep_xe(const float* __restrict__ x, const float* __restrict__ ea) {
    int idx = blockIdx.x * blockDim.x + threadIdx.x;
    int stride = gridDim.x * blockDim.x;
    const int NX = N_NODES * D_IN / 4, NE = N_EDGES * D_EDGE / 4;
    for (int i = idx; i < NX; i += stride) {
        float4 v = __ldg((const float4*)x + i);
        __half2 h0 = __floats2half2_rn(v.x, v.y), h1 = __floats2half2_rn(v.z, v.w);
        *((uint2*)g_xh + i) = make_uint2(h2_bits(h0), h2_bits(h1));
    }
    for (int i = idx; i < NE; i += stride) {
        float4 v = __ldg((const float4*)ea + i);
        __half2 h0 = __floats2half2_rn(v.x, v.y), h1 = __floats2half2_rn(v.z, v.w);
        *((uint2*)g_eah + i) = make_uint2(h2_bits(h0), h2_bits(h1));
    }
}

__global__ void prep_w(const float* __restrict__ We1, const float* __restrict__ We2,
                       const float* __restrict__ Wg,  const float* __restrict__ Wn) {
    int i = blockIdx.x * blockDim.x + threadIdx.x;
    int n = i & 127;
    if (i < K1 * D_HID) {
        int k = i >> 7;
        uint32_t off = (uint32_t)k * 256 + (((n >> 3) ^ (k & 7)) * 16) + (n & 7) * 2;
        *(__half*)((char*)g_B1h + off) = __float2half_rn(We1[k * D_HID + n]);
        return;
    }
    i -= K1 * D_HID;
    if (i < D_HID * D_HID) {
        int k = i >> 7; n = i & 127;
        uint32_t off = (uint32_t)k * 256 + (((n >> 3) ^ (k & 7)) * 16) + (n & 7) * 2;
        *(__half*)((char*)g_B2h + off) = __float2half_rn(We2[k * D_HID + n]);
        return;
    }
    i -= D_HID * D_HID;
    if (i < 2 * D_HID * D_HID) {
        int k = i >> 7; n = i & 127;
        uint32_t off = (uint32_t)k * 256 + (((n >> 3) ^ (k & 7)) * 16) + (n & 7) * 2;
        *(__half*)((char*)g_Bgh + off) = __float2half_rn(Wg[k * D_HID + n]);
        return;
    }
    i -= 2 * D_HID * D_HID;
    if (i < 2 * D_HID * D_HID) {
        int k = i >> 7; n = i & 127;
        uint32_t off = (uint32_t)k * 256 + (((n >> 3) ^ (k & 7)) * 16) + (n & 7) * 2;
        *(__half*)((char*)g_Bnh + off) = __float2half_rn(Wn[k * D_HID + n]);
    }
}

// ============================================================================
// Edge block: persistent CTAs, 128-edge tiles, 8 warps (4x2 grid of 32x64
// warp tiles, LDSM:MMA = 0.375), resident weights, overlapped cp.async gather.
// ============================================================================
__global__ __launch_bounds__(ETHREADS, 1) void edge_kernel(
    const int* __restrict__ eidx,
    const float* __restrict__ be1, const float* __restrict__ be2)
{
    extern __shared__ char smem[];
    const uint32_t sb = smem_u32(smem);
    const int tid = threadIdx.x, wid = tid >> 5, lane = tid & 31;
    const int wm = wid & 3, wn = wid >> 2;   // wm: 32-row slab; wn: 64-col half

    int*   sIdx = (int*)(smem + E_IDX);
    float* sBE1 = (float*)(smem + E_BE1);
    float* sBE2 = (float*)(smem + E_BE2);
    float* sStg = (float*)(smem + E_H);

    if (tid < D_HID) { sBE1[tid] = be1[tid]; sBE2[tid] = be2[tid]; }

    // resident weights
    {
        const uint4* s1 = (const uint4*)g_B1h; uint4* d1 = (uint4*)(smem + E_W1);
        #pragma unroll
        for (int i = 0; i < 18; i++) d1[tid + i * 256] = s1[tid + i * 256];
        const uint4* s2 = (const uint4*)g_B2h; uint4* d2 = (uint4*)(smem + E_W2);
        #pragma unroll
        for (int i = 0; i < 8; i++) d2[tid + i * 256] = s2[tid + i * 256];
    }

    const int lo15 = lane & 15;
    const int hi   = lane >> 4;
    const int lo7  = lane & 7;
    uint32_t bXor[4];
    #pragma unroll
    for (int p = 0; p < 4; p++) bXor[p] = (uint32_t)(((wn * 8 + 2 * p + hi) ^ lo7) * 16);

    const uint32_t aBase0 = sb + E_A + ((32 * wm + lo15) * A_STRIDE + hi * 8) * 2;
    const uint32_t aBase1 = aBase0 + 16 * A_STRIDE * 2;
    const uint32_t hBase0 = sb + E_H + ((32 * wm + lo15) * H_STRIDE + hi * 8) * 2;
    const uint32_t hBase1 = hBase0 + 16 * H_STRIDE * 2;
    const uint32_t w1Base = sb + E_W1 + lo15 * 256;
    const uint32_t w2Base = sb + E_W2 + lo15 * 256;

    const int rowLo = 32 * wm + (lane >> 2);
    const int colLo = wn * 64 + (lane & 3) * 2;

    int t = blockIdx.x;
    int pb = 0;
    if (tid < TILE_E)            sIdx[tid] = eidx[t * TILE_E + tid];
    else if (tid < 2 * TILE_E)   sIdx[tid] = eidx[N_EDGES + t * TILE_E + (tid - TILE_E)];
    __syncthreads();
    // gather(t): 4608 cp.async over 256 threads
    {
        const int* sS = sIdx, *sD = sIdx + TILE_E;
        #pragma unroll
        for (int it = 0; it < 18; it++) {
            int i = tid + it * ETHREADS;
            int row = i / 36, u = i - row * 36;
            const void* src;
            if (u < 16)      src = g_xh + (size_t)sS[row] * D_IN + u * 8;
            else if (u < 32) src = g_xh + (size_t)sD[row] * D_IN + (u - 16) * 8;
            else             src = g_eah + (size_t)(t * TILE_E + row) * D_EDGE + (u - 32) * 8;
            cpa16(sb + E_A + row * 592 + u * 16, src);
        }
        CPA_COMMIT();
    }

    for (; t < NT2; t += EDGE_GRID, pb ^= 1) {
        const int tn = t + EDGE_GRID;
        if (tn < NT2) {
            if (tid < TILE_E)          sIdx[(pb ^ 1) * 256 + tid] = eidx[tn * TILE_E + tid];
            else if (tid < 2 * TILE_E) sIdx[(pb ^ 1) * 256 + tid] =
                                           eidx[N_EDGES + tn * TILE_E + (tid - TILE_E)];
        }
        CPA_WAIT0();
        __syncthreads();   // A(t) ready; idx(tn) visible

        float c[2][8][4];
        #pragma unroll
        for (int mi = 0; mi < 2; mi++)
            #pragma unroll
            for (int nt = 0; nt < 8; nt++)
                #pragma unroll
                for (int j = 0; j < 4; j++) c[mi][nt][j] = 0.0f;

        // ---- layer 1: K = 288 ----
        #pragma unroll
        for (int ks = 0; ks < 18; ks++) {
            uint32_t a0[4], a1[4];
            ldm_x4(a0, aBase0 + ks * 32);
            ldm_x4(a1, aBase1 + ks * 32);
            uint32_t bk = w1Base + ks * 4096;
            #pragma unroll
            for (int p = 0; p < 4; p++) {
                uint32_t b[4];
                ldm_x4_t(b, bk + bXor[p]);
                mma16816(c[0][2 * p + 0], a0, b[0], b[1]);
                mma16816(c[0][2 * p + 1], a0, b[2], b[3]);
                mma16816(c[1][2 * p + 0], a1, b[0], b[1]);
                mma16816(c[1][2 * p + 1], a1, b[2], b[3]);
            }
        }
        __syncthreads();   // all layer-1 A reads done -> A free

        // issue gather(tn) into A (overlaps epilogue1 + layer2 + scatter)
        if (tn < NT2) {
            const int* sS = sIdx + (pb ^ 1) * 256, *sD = sS + TILE_E;
            #pragma unroll
            for (int it = 0; it < 18; it++) {
                int i = tid + it * ETHREADS;
                int row = i / 36, u = i - row * 36;
                const void* src;
                if (u < 16)      src = g_xh + (size_t)sS[row] * D_IN + u * 8;
                else if (u < 32) src = g_xh + (size_t)sD[row] * D_IN + (u - 16) * 8;
                else             src = g_eah + (size_t)(tn * TILE_E + row) * D_EDGE + (u - 32) * 8;
                cpa16(sb + E_A + row * 592 + u * 16, src);
            }
            CPA_COMMIT();
        }

        // epilogue 1: bias+relu -> fp16 H
        #pragma unroll
        for (int mi = 0; mi < 2; mi++) {
            int r0 = rowLo + 16 * mi;
            #pragma unroll
            for (int nt = 0; nt < 8; nt++) {
                int col = nt * 8 + colLo;
                float2 bb = *(const float2*)(sBE1 + col);
                float v0 = fmaxf(c[mi][nt][0] + bb.x, 0.f);
                float v1 = fmaxf(c[mi][nt][1] + bb.y, 0.f);
                float v2 = fmaxf(c[mi][nt][2] + bb.x, 0.f);
                float v3 = fmaxf(c[mi][nt][3] + bb.y, 0.f);
                *(uint32_t*)(smem + E_H + (r0 * H_STRIDE + col) * 2) =
                    h2_bits(__floats2half2_rn(v0, v1));
                *(uint32_t*)(smem + E_H + ((r0 + 8) * H_STRIDE + col) * 2) =
                    h2_bits(__floats2half2_rn(v2, v3));
            }
        }
        __syncthreads();   // H visible

        #pragma unroll
        for (int mi = 0; mi < 2; mi++)
            #pragma unroll
            for (int nt = 0; nt < 8; nt++)
                #pragma unroll
                for (int j = 0; j < 4; j++) c[mi][nt][j] = 0.0f;

        // ---- layer 2: K = 128 ----
        #pragma unroll
        for (int ks = 0; ks < 8; ks++) {
            uint32_t a0[4], a1[4];
            ldm_x4(a0, hBase0 + ks * 32);
            ldm_x4(a1, hBase1 + ks * 32);
            uint32_t bk = w2Base + ks * 4096;
            #pragma unroll
            for (int p = 0; p < 4; p++) {
                uint32_t b[4];
                ldm_x4_t(b, bk + bXor[p]);
                mma16816(c[0][2 * p + 0], a0, b[0], b[1]);
                mma16816(c[0][2 * p + 1], a0, b[2], b[3]);
                mma16816(c[1][2 * p + 0], a1, b[0], b[1]);
                mma16816(c[1][2 * p + 1], a1, b[2], b[3]);
            }
        }
        __syncthreads();   // all H reads done before staging overwrites

        const int* sDstP = sIdx + pb * 256 + TILE_E;

        // epilogue 2: two 64-col passes through f32 staging -> v4 scatter
        #pragma unroll
        for (int p = 0; p < 2; p++) {
            if (wn == p) {
                #pragma unroll
                for (int mi = 0; mi < 2; mi++) {
                    int r0 = rowLo + 16 * mi;
                    #pragma unroll
                    for (int nt = 0; nt < 8; nt++) {
                        int col = nt * 8 + colLo;
                        int cl = col & 63;
                        float2 bb = *(const float2*)(sBE2 + col);
                        *(float2*)(sStg + r0 * STG_STRIDE + cl) =
                            make_float2(fmaxf(c[mi][nt][0] + bb.x, 0.f),
                                        fmaxf(c[mi][nt][1] + bb.y, 0.f));
                        *(float2*)(sStg + (r0 + 8) * STG_STRIDE + cl) =
                            make_float2(fmaxf(c[mi][nt][2] + bb.x, 0.f),
                                        fmaxf(c[mi][nt][3] + bb.y, 0.f));
                    }
                }
            }
            __syncthreads();
            #pragma unroll
            for (int i = 0; i < 8; i++) {
                int v = tid + i * ETHREADS;      // 2048 v4 slots
                int row = v >> 4, c4 = v & 15;
                float4 val = *(const float4*)(sStg + row * STG_STRIDE + c4 * 4);
                red_add_v4(g_agg + (size_t)sDstP[row] * D_HID + p * 64 + c4 * 4,
                           val.x, val.y, val.z, val.w);
            }
            __syncthreads();
        }
    }
}

// ============================================================================
// Node block: HMMA fp16 (unchanged, passing).
// ============================================================================
__global__ __launch_bounds__(256, 2) void node_kernel(
    const float* __restrict__ x,
    const float* __restrict__ bg, const float* __restrict__ bn,
    const int* __restrict__ batch, float* __restrict__ xw_out)
{
    extern __shared__ char smem[];
    const uint32_t sb = smem_u32(smem);
    const int tid = threadIdx.x, wid = tid >> 5, lane = tid & 31;
    const int wm = wid & 3, wn = wid >> 2;
    const int nBase = blockIdx.x * TILE_M;

    float* sBG = (float*)(smem + N_BG);
    float* sBN = (float*)(smem + N_BN);
    if (tid < D_HID) { sBG[tid] = bg[tid]; sBN[tid] = bn[tid]; }

    const int lo15 = lane & 15;
    const int hi   = lane >> 4;
    const int lo7  = lane & 7;
    uint32_t bXor[4];
    #pragma unroll
    for (int p = 0; p < 4; p++) bXor[p] = (uint32_t)(((wn * 8 + 2 * p + hi) ^ lo7) * 16);

    const uint32_t aBase = sb + N_A + ((16 * wm + lo15) * A_STRIDE + hi * 8) * 2;
    const uint32_t wBase = sb + N_W + lo15 * 256;

    const int rowLo = 16 * wm + (lane >> 2);
    const int rowHi = rowLo + 8;
    const int colLo = wn * 64 + (lane & 3) * 2;
    const int nLo = nBase + rowLo, nHi = nBase + rowHi;
    const int bLo = batch[min(nLo, N_NODES - 1)];
    const int bHi = batch[min(nHi, N_NODES - 1)];

    #pragma unroll
    for (int it = 0; it < 16; it++) {
        int i = tid + it * 256;
        int row = i >> 6, u = i & 63;
        int k0 = u * 4;
        int n = min(nBase + row, N_NODES - 1);
        float4 v = (k0 < D_IN)
            ? __ldg((const float4*)(x + (size_t)n * D_IN + k0))
            : *(const float4*)(g_agg + (size_t)n * D_HID + (k0 - D_IN));
        __half2 h0 = __floats2half2_rn(v.x, v.y);
        __half2 h1 = __floats2half2_rn(v.z, v.w);
        *reinterpret_cast<uint2*>(smem + N_A + (row * A_STRIDE + k0) * 2) =
            make_uint2(h2_bits(h0), h2_bits(h1));
    }
    {
        const uint4* s = (const uint4*)g_Bgh; uint4* d = (uint4*)(smem + N_W);
        #pragma unroll
        for (int i = 0; i < 16; i++) d[tid + i * 256] = s[tid + i * 256];
    }
    __syncthreads();

    float c[8][4];
    #pragma unroll
    for (int nt = 0; nt < 8; nt++)
        #pragma unroll
        for (int j = 0; j < 4; j++) c[nt][j] = 0.0f;

    #pragma unroll
    for (int ks = 0; ks < 16; ks++) {
        uint32_t a[4];
        ldm_x4(a, aBase + ks * 32);
        uint32_t bk = wBase + ks * 4096;
        #pragma unroll
        for (int p = 0; p < 4; p++) {
            uint32_t b[4];
            ldm_x4_t(b, bk + bXor[p]);
            mma16816(c[2 * p + 0], a, b[0], b[1]);
            mma16816(c[2 * p + 1], a, b[2], b[3]);
        }
    }

    float gate[8][4];
    #pragma unroll
    for (int nt = 0; nt < 8; nt++) {
        int col = nt * 8 + colLo;
        float2 bb = *(const float2*)(sBG + col);
        gate[nt][0] = 1.0f / (1.0f + __expf(-(c[nt][0] + bb.x)));
        gate[nt][1] = 1.0f / (1.0f + __expf(-(c[nt][1] + bb.y)));
        gate[nt][2] = 1.0f / (1.0f + __expf(-(c[nt][2] + bb.x)));
        gate[nt][3] = 1.0f / (1.0f + __expf(-(c[nt][3] + bb.y)));
        if (nLo < N_NODES)
            *(float2*)(xw_out + (size_t)nLo * D_HID + col) = make_float2(gate[nt][0], gate[nt][1]);
        if (nHi < N_NODES)
            *(float2*)(xw_out + (size_t)nHi * D_HID + col) = make_float2(gate[nt][2], gate[nt][3]);
    }
    if (wn == 0 && (lane & 3) == 0) {
        if (nLo < N_NODES) atomicAdd(&g_counts[bLo], 1.0f);
        if (nHi < N_NODES) atomicAdd(&g_counts[bHi], 1.0f);
    }

    __syncthreads();
    {
        const uint4* s = (const uint4*)g_Bnh; uint4* d = (uint4*)(smem + N_W);
        #pragma unroll
        for (int i = 0; i < 16; i++) d[tid + i * 256] = s[tid + i * 256];
    }
    __syncthreads();

    #pragma unroll
    for (int nt = 0; nt < 8; nt++)
        #pragma unroll
        for (int j = 0; j < 4; j++) c[nt][j] = 0.0f;

    #pragma unroll
    for (int ks = 0; ks < 16; ks++) {
        uint32_t a[4];
        ldm_x4(a, aBase + ks * 32);
        uint32_t bk = wBase + ks * 4096;
        #pragma unroll
        for (int p = 0; p < 4; p++) {
            uint32_t b[4];
            ldm_x4_t(b, bk + bXor[p]);
            mma16816(c[2 * p + 0], a, b[0], b[1]);
            mma16816(c[2 * p + 1], a, b[2], b[3]);
        }
    }

    #pragma unroll
    for (int nt = 0; nt < 8; nt++) {
        int col = nt * 8 + colLo;
        float2 bb = *(const float2*)(sBN + col);
        float x0 = gate[nt][0] * fmaxf(c[nt][0] + bb.x, 0.f);
        float x1 = gate[nt][1] * fmaxf(c[nt][1] + bb.y, 0.f);
        float x2 = gate[nt][2] * fmaxf(c[nt][2] + bb.x, 0.f);
        float x3 = gate[nt][3] * fmaxf(c[nt][3] + bb.y, 0.f);
        if (nLo < N_NODES) red_add_v2(g_pooled + (size_t)bLo * D_HID + col, x0, x1);
        if (nHi < N_NODES) red_add_v2(g_pooled + (size_t)bHi * D_HID + col, x2, x3);
    }
}

// ---------------------------------------------------------------------------
__global__ __launch_bounds__(64) void global_kernel(
    const float* __restrict__ u, const float* __restrict__ Wu,
    const float* __restrict__ bu, float* __restrict__ out)
{
    __shared__ float sin_[D_GLOB + D_HID];
    int g = blockIdx.x;
    int j = threadIdx.x;
    float cnt = fmaxf(g_counts[g], 1.0f);
    sin_[j] = u[g * D_GLOB + j];
    sin_[D_GLOB + j]      = g_pooled[g * D_HID + j] / cnt;
    sin_[D_GLOB + 64 + j] = g_pooled[g * D_HID + 64 + j] / cnt;
    __syncthreads();
    float acc = bu[j];
    #pragma unroll 8
    for (int k = 0; k < D_GLOB + D_HID; k++)
        acc = fmaf(sin_[k], Wu[k * D_GLOB + j], acc);
    out[g * D_GLOB + j] = fmaxf(acc, 0.0f);
}

// ---------------------------------------------------------------------------
extern "C" void kernel_launch(void* const* d_in, const int* in_sizes, int n_in,
                              void* d_out, int out_size)
{
    const float* x    = (const float*)d_in[0];
    const int*   eidx = (const int*)  d_in[1];
    const float* ea   = (const float*)d_in[2];
    const float* u    = (const float*)d_in[3];
    const int*   batch= (const int*)  d_in[4];
    const float* We1  = (const float*)d_in[5];
    const float* be1  = (const float*)d_in[6];
    const float* We2  = (const float*)d_in[7];
    const float* be2  = (const float*)d_in[8];
    const float* Wg   = (const float*)d_in[9];
    const float* bg   = (const float*)d_in[10];
    const float* Wn   = (const float*)d_in[11];
    const float* bn   = (const float*)d_in[12];
    const float* Wu   = (const float*)d_in[13];
    const float* bu   = (const float*)d_in[14];

    float* out   = (float*)d_out;
    float* u_new = out;
    float* xw    = out + N_GRAPHS * D_GLOB;

    cudaFuncSetAttribute(edge_kernel, cudaFuncAttributeMaxDynamicSharedMemorySize, E_TOTAL);
    cudaFuncSetAttribute(node_kernel, cudaFuncAttributeMaxDynamicSharedMemorySize, N_TOTAL);

    zero_kernel<<<2048, 256>>>();
    prep_xe<<<2048, 256>>>(x, ea);
    int prep_elems = K1 * D_HID + D_HID * D_HID + 4 * D_HID * D_HID;
    prep_w<<<(prep_elems + 255) / 256, 256>>>(We1, We2, Wg, Wn);
    edge_kernel<<<EDGE_GRID, ETHREADS, E_TOTAL>>>(eidx, be1, be2);
    node_kernel<<<(N_NODES + TILE_M - 1) / TILE_M, 256, N_TOTAL>>>(x, bg, bn, batch, xw);
    global_kernel<<<N_GRAPHS, 64>>>(u, Wu, bu, u_new);
}

// round 10
// speedup vs baseline: 1.0939x; 1.0939x over previous
#include <cuda_runtime.h>
#include <cuda_fp16.h>
#include <math.h>
#include <stdint.h>

#define N_NODES 50000
#define N_EDGES 800000
#define N_GRAPHS 512
#define D_IN 128
#define D_EDGE 32
#define D_HID 128
#define D_GLOB 64
#define K1 288

#define TILE_M 64                  /* node kernel tile */
#define TILE_E 128                 /* edge kernel tile */
#define NT2 (N_EDGES / TILE_E)     /* 6250 tiles */
#define EDGE_GRID 148
#define ETHREADS 512               /* 16 warps: 4 wm x 4 wn, 32x32 warp tiles */

#define A_STRIDE 296               /* halves: 592 B rows */
#define H_STRIDE 136               /* halves: 272 B rows */

// ---- scratch ----
__device__ float  g_agg[N_NODES * D_HID];
__device__ float  g_pooled[N_GRAPHS * D_HID];
__device__ float  g_counts[N_GRAPHS];
__device__ __half g_xh[N_NODES * D_IN];
__device__ __half g_eah[N_EDGES * D_EDGE];
// fp16 weight images: byte(k,n) = k*256 + (((n>>3)^(k&7))*16) + (n&7)*2
__device__ __half g_B1h[K1 * D_HID];
__device__ __half g_B2h[D_HID * D_HID];
__device__ __half g_Bgh[2 * D_HID * D_HID];
__device__ __half g_Bnh[2 * D_HID * D_HID];

// ---- edge kernel SMEM layout (bytes) ----
#define E_IDX   0                          /* 2 bufs x 256 ints = 2048 */
#define E_BE1   2048
#define E_BE2   2560
#define E_A     3072                       /* 128 x 592 = 75776 */
#define E_H     (E_A + 75776)              /* 78848: 128 x 272 = 34816 */
#define E_W1    (E_H + 34816)              /* 113664: 73728 */
#define E_W2    (E_W1 + 73728)             /* 187392: 32768 */
#define E_TOTAL (E_W2 + 32768)             /* 220160 */

// ---- node kernel SMEM layout ----
#define N_BG    0
#define N_BN    512
#define N_A     1024
#define N_W     (N_A + 37888)
#define N_TOTAL (N_W + 65536)

// ============================ PTX helpers ===================================
__device__ __forceinline__ uint32_t smem_u32(const void* p) {
    uint32_t a;
    asm("{ .reg .u64 t; cvta.to.shared.u64 t, %1; cvt.u32.u64 %0, t; }" : "=r"(a) : "l"(p));
    return a;
}
__device__ __forceinline__ void ldm_x4(uint32_t* r, uint32_t addr) {
    asm volatile("ldmatrix.sync.aligned.m8n8.x4.shared.b16 {%0,%1,%2,%3}, [%4];"
                 : "=r"(r[0]), "=r"(r[1]), "=r"(r[2]), "=r"(r[3]) : "r"(addr));
}
__device__ __forceinline__ void ldm_x4_t(uint32_t* r, uint32_t addr) {
    asm volatile("ldmatrix.sync.aligned.m8n8.x4.trans.shared.b16 {%0,%1,%2,%3}, [%4];"
                 : "=r"(r[0]), "=r"(r[1]), "=r"(r[2]), "=r"(r[3]) : "r"(addr));
}
__device__ __forceinline__ void mma16816(float* c, const uint32_t* a, uint32_t b0, uint32_t b1) {
    asm volatile(
        "mma.sync.aligned.m16n8k16.row.col.f32.f16.f16.f32 "
        "{%0,%1,%2,%3}, {%4,%5,%6,%7}, {%8,%9}, {%0,%1,%2,%3};"
        : "+f"(c[0]), "+f"(c[1]), "+f"(c[2]), "+f"(c[3])
        : "r"(a[0]), "r"(a[1]), "r"(a[2]), "r"(a[3]), "r"(b0), "r"(b1));
}
__device__ __forceinline__ void red_add_v4(float* p, float a, float b, float c, float d) {
    asm volatile("red.global.add.v4.f32 [%0], {%1, %2, %3, %4};"
                 :: "l"(p), "f"(a), "f"(b), "f"(c), "f"(d) : "memory");
}
__device__ __forceinline__ void red_add_v2(float* p, float a, float b) {
    asm volatile("red.global.add.v2.f32 [%0], {%1, %2};" :: "l"(p), "f"(a), "f"(b) : "memory");
}
__device__ __forceinline__ void cpa16(uint32_t dst, const void* src) {
    asm volatile("cp.async.cg.shared.global [%0], [%1], 16;" :: "r"(dst), "l"(src) : "memory");
}
#define CPA_COMMIT() asm volatile("cp.async.commit_group;" ::: "memory")
#define CPA_WAIT0()  asm volatile("cp.async.wait_group 0;" ::: "memory")
__device__ __forceinline__ uint32_t h2_bits(__half2 h) {
    return *reinterpret_cast<uint32_t*>(&h);
}

// ============================================================================
__global__ void zero_kernel() {
    int idx = blockIdx.x * blockDim.x + threadIdx.x;
    int stride = gridDim.x * blockDim.x;
    float4 z = make_float4(0.f, 0.f, 0.f, 0.f);
    float4* a4 = (float4*)g_agg;
    for (int i = idx; i < N_NODES * D_HID / 4; i += stride) a4[i] = z;
    for (int i = idx; i < N_GRAPHS * D_HID; i += stride) g_pooled[i] = 0.0f;
    for (int i = idx; i < N_GRAPHS; i += stride) g_counts[i] = 0.0f;
}

__global__ void prep_xe(const float* __restrict__ x, const float* __restrict__ ea) {
    int idx = blockIdx.x * blockDim.x + threadIdx.x;
    int stride = gridDim.x * blockDim.x;
    const int NX = N_NODES * D_IN / 4, NE = N_EDGES * D_EDGE / 4;
    for (int i = idx; i < NX; i += stride) {
        float4 v = __ldg((const float4*)x + i);
        __half2 h0 = __floats2half2_rn(v.x, v.y), h1 = __floats2half2_rn(v.z, v.w);
        *((uint2*)g_xh + i) = make_uint2(h2_bits(h0), h2_bits(h1));
    }
    for (int i = idx; i < NE; i += stride) {
        float4 v = __ldg((const float4*)ea + i);
        __half2 h0 = __floats2half2_rn(v.x, v.y), h1 = __floats2half2_rn(v.z, v.w);
        *((uint2*)g_eah + i) = make_uint2(h2_bits(h0), h2_bits(h1));
    }
}

__global__ void prep_w(const float* __restrict__ We1, const float* __restrict__ We2,
                       const float* __restrict__ Wg,  const float* __restrict__ Wn) {
    int i = blockIdx.x * blockDim.x + threadIdx.x;
    int n = i & 127;
    if (i < K1 * D_HID) {
        int k = i >> 7;
        uint32_t off = (uint32_t)k * 256 + (((n >> 3) ^ (k & 7)) * 16) + (n & 7) * 2;
        *(__half*)((char*)g_B1h + off) = __float2half_rn(We1[k * D_HID + n]);
        return;
    }
    i -= K1 * D_HID;
    if (i < D_HID * D_HID) {
        int k = i >> 7; n = i & 127;
        uint32_t off = (uint32_t)k * 256 + (((n >> 3) ^ (k & 7)) * 16) + (n & 7) * 2;
        *(__half*)((char*)g_B2h + off) = __float2half_rn(We2[k * D_HID + n]);
        return;
    }
    i -= D_HID * D_HID;
    if (i < 2 * D_HID * D_HID) {
        int k = i >> 7; n = i & 127;
        uint32_t off = (uint32_t)k * 256 + (((n >> 3) ^ (k & 7)) * 16) + (n & 7) * 2;
        *(__half*)((char*)g_Bgh + off) = __float2half_rn(Wg[k * D_HID + n]);
        return;
    }
    i -= 2 * D_HID * D_HID;
    if (i < 2 * D_HID * D_HID) {
        int k = i >> 7; n = i & 127;
        uint32_t off = (uint32_t)k * 256 + (((n >> 3) ^ (k & 7)) * 16) + (n & 7) * 2;
        *(__half*)((char*)g_Bnh + off) = __float2half_rn(Wn[k * D_HID + n]);
    }
}

// ============================================================================
// Edge block: persistent CTAs, 128-edge tiles, 16 warps (4x4 of 32x32 tiles),
// resident weights, overlapped cp.async gather, shuffle + direct v4 scatter.
// ============================================================================
__global__ __launch_bounds__(ETHREADS, 1) void edge_kernel(
    const int* __restrict__ eidx,
    const float* __restrict__ be1, const float* __restrict__ be2)
{
    extern __shared__ char smem[];
    const uint32_t sb = smem_u32(smem);
    const int tid = threadIdx.x, wid = tid >> 5, lane = tid & 31;
    const int wm = wid & 3, wn = wid >> 2;

    int*   sIdx = (int*)(smem + E_IDX);
    float* sBE1 = (float*)(smem + E_BE1);
    float* sBE2 = (float*)(smem + E_BE2);

    if (tid < D_HID) { sBE1[tid] = be1[tid]; sBE2[tid] = be2[tid]; }

    // resident weights
    {
        const uint4* s1 = (const uint4*)g_B1h; uint4* d1 = (uint4*)(smem + E_W1);
        #pragma unroll
        for (int i = 0; i < 9; i++) d1[tid + i * 512] = s1[tid + i * 512];
        const uint4* s2 = (const uint4*)g_B2h; uint4* d2 = (uint4*)(smem + E_W2);
        #pragma unroll
        for (int i = 0; i < 4; i++) d2[tid + i * 512] = s2[tid + i * 512];
    }

    const int lo15 = lane & 15;
    const int hi   = lane >> 4;
    const int lo7  = lane & 7;
    uint32_t bXor[2];
    #pragma unroll
    for (int p = 0; p < 2; p++) bXor[p] = (uint32_t)(((wn * 4 + 2 * p + hi) ^ lo7) * 16);

    const uint32_t aBase0 = sb + E_A + ((32 * wm + lo15) * A_STRIDE + hi * 8) * 2;
    const uint32_t aBase1 = aBase0 + 16 * A_STRIDE * 2;
    const uint32_t hBase0 = sb + E_H + ((32 * wm + lo15) * H_STRIDE + hi * 8) * 2;
    const uint32_t hBase1 = hBase0 + 16 * H_STRIDE * 2;
    const uint32_t w1Base = sb + E_W1 + lo15 * 256;
    const uint32_t w2Base = sb + E_W2 + lo15 * 256;

    const int rowLo = 32 * wm + (lane >> 2);
    const int colLo = wn * 32 + (lane & 3) * 2;
    const int odd   = lane & 1;
    const int col4  = wn * 32 + ((lane & 3) >> 1) * 4;   // v4 col base per pair

    int t = blockIdx.x;
    int pb = 0;
    if (tid < TILE_E)            sIdx[tid] = eidx[t * TILE_E + tid];
    else if (tid < 2 * TILE_E)   sIdx[tid] = eidx[N_EDGES + t * TILE_E + (tid - TILE_E)];
    __syncthreads();
    // gather(t): 4608 cp.async
    {
        const int* sS = sIdx, *sD = sIdx + TILE_E;
        #pragma unroll
        for (int it = 0; it < 9; it++) {
            int i = tid + it * ETHREADS;
            int row = i / 36, u = i - row * 36;
            const void* src;
            if (u < 16)      src = g_xh + (size_t)sS[row] * D_IN + u * 8;
            else if (u < 32) src = g_xh + (size_t)sD[row] * D_IN + (u - 16) * 8;
            else             src = g_eah + (size_t)(t * TILE_E + row) * D_EDGE + (u - 32) * 8;
            cpa16(sb + E_A + row * 592 + u * 16, src);
        }
        CPA_COMMIT();
    }

    for (; t < NT2; t += EDGE_GRID, pb ^= 1) {
        const int tn = t + EDGE_GRID;
        if (tn < NT2) {
            if (tid < TILE_E)          sIdx[(pb ^ 1) * 256 + tid] = eidx[tn * TILE_E + tid];
            else if (tid < 2 * TILE_E) sIdx[(pb ^ 1) * 256 + tid] =
                                           eidx[N_EDGES + tn * TILE_E + (tid - TILE_E)];
        }
        CPA_WAIT0();
        __syncthreads();   // A(t) ready; idx(tn) visible; prior-tile H reads done

        float c[2][4][4];
        #pragma unroll
        for (int mi = 0; mi < 2; mi++)
            #pragma unroll
            for (int nt = 0; nt < 4; nt++)
                #pragma unroll
                for (int j = 0; j < 4; j++) c[mi][nt][j] = 0.0f;

        // ---- layer 1: K = 288 ----
        #pragma unroll
        for (int ks = 0; ks < 18; ks++) {
            uint32_t a0[4], a1[4];
            ldm_x4(a0, aBase0 + ks * 32);
            ldm_x4(a1, aBase1 + ks * 32);
            uint32_t bk = w1Base + ks * 4096;
            #pragma unroll
            for (int p = 0; p < 2; p++) {
                uint32_t b[4];
                ldm_x4_t(b, bk + bXor[p]);
                mma16816(c[0][2 * p + 0], a0, b[0], b[1]);
                mma16816(c[0][2 * p + 1], a0, b[2], b[3]);
                mma16816(c[1][2 * p + 0], a1, b[0], b[1]);
                mma16816(c[1][2 * p + 1], a1, b[2], b[3]);
            }
        }
        __syncthreads();   // all layer-1 A reads done -> A free

        // issue gather(tn) into A (overlaps epilogue1 + layer2 + scatter)
        if (tn < NT2) {
            const int* sS = sIdx + (pb ^ 1) * 256, *sD = sS + TILE_E;
            #pragma unroll
            for (int it = 0; it < 9; it++) {
                int i = tid + it * ETHREADS;
                int row = i / 36, u = i - row * 36;
                const void* src;
                if (u < 16)      src = g_xh + (size_t)sS[row] * D_IN + u * 8;
                else if (u < 32) src = g_xh + (size_t)sD[row] * D_IN + (u - 16) * 8;
                else             src = g_eah + (size_t)(tn * TILE_E + row) * D_EDGE + (u - 32) * 8;
                cpa16(sb + E_A + row * 592 + u * 16, src);
            }
            CPA_COMMIT();
        }

        // epilogue 1: bias+relu -> fp16 H
        #pragma unroll
        for (int mi = 0; mi < 2; mi++) {
            int r0 = rowLo + 16 * mi;
            #pragma unroll
            for (int nt = 0; nt < 4; nt++) {
                int col = nt * 8 + colLo;
                float2 bb = *(const float2*)(sBE1 + col);
                float v0 = fmaxf(c[mi][nt][0] + bb.x, 0.f);
                float v1 = fmaxf(c[mi][nt][1] + bb.y, 0.f);
                float v2 = fmaxf(c[mi][nt][2] + bb.x, 0.f);
                float v3 = fmaxf(c[mi][nt][3] + bb.y, 0.f);
                *(uint32_t*)(smem + E_H + (r0 * H_STRIDE + col) * 2) =
                    h2_bits(__floats2half2_rn(v0, v1));
                *(uint32_t*)(smem + E_H + ((r0 + 8) * H_STRIDE + col) * 2) =
                    h2_bits(__floats2half2_rn(v2, v3));
            }
        }
        __syncthreads();   // H visible

        #pragma unroll
        for (int mi = 0; mi < 2; mi++)
            #pragma unroll
            for (int nt = 0; nt < 4; nt++)
                #pragma unroll
                for (int j = 0; j < 4; j++) c[mi][nt][j] = 0.0f;

        // ---- layer 2: K = 128 ----
        #pragma unroll
        for (int ks = 0; ks < 8; ks++) {
            uint32_t a0[4], a1[4];
            ldm_x4(a0, hBase0 + ks * 32);
            ldm_x4(a1, hBase1 + ks * 32);
            uint32_t bk = w2Base + ks * 4096;
            #pragma unroll
            for (int p = 0; p < 2; p++) {
                uint32_t b[4];
                ldm_x4_t(b, bk + bXor[p]);
                mma16816(c[0][2 * p + 0], a0, b[0], b[1]);
                mma16816(c[0][2 * p + 1], a0, b[2], b[3]);
                mma16816(c[1][2 * p + 0], a1, b[0], b[1]);
                mma16816(c[1][2 * p + 1], a1, b[2], b[3]);
            }
        }

        // epilogue 2: bias+relu, pair-shuffle -> direct red.global.add.v4
        // even lane emits rowT v4, odd lane emits rowB v4 (cols col4..col4+3)
        const int* sDstP = sIdx + pb * 256 + TILE_E;
        #pragma unroll
        for (int mi = 0; mi < 2; mi++) {
            int rT = rowLo + 16 * mi;
            int rB = rT + 8;
            float* dp = g_agg + (size_t)sDstP[odd ? rB : rT] * D_HID;
            #pragma unroll
            for (int nt = 0; nt < 4; nt++) {
                int col = nt * 8 + colLo;
                float2 bb = *(const float2*)(sBE2 + col);
                float t0 = fmaxf(c[mi][nt][0] + bb.x, 0.f);
                float t1 = fmaxf(c[mi][nt][1] + bb.y, 0.f);
                float b0 = fmaxf(c[mi][nt][2] + bb.x, 0.f);
                float b1 = fmaxf(c[mi][nt][3] + bb.y, 0.f);
                float2 send = odd ? make_float2(t0, t1) : make_float2(b0, b1);
                unsigned long long sv = *reinterpret_cast<unsigned long long*>(&send);
                unsigned long long rvu = __shfl_xor_sync(0xffffffffu, sv, 1);
                float2 rv = *reinterpret_cast<float2*>(&rvu);
                if (!odd) red_add_v4(dp + nt * 8 + col4 - wn * 32 + wn * 32, t0, t1, rv.x, rv.y);
                else      red_add_v4(dp + nt * 8 + col4 - wn * 32 + wn * 32, rv.x, rv.y, b0, b1);
            }
        }
        // no trailing sync: loop-top __syncthreads orders scatter vs next tile
    }
}

// ============================================================================
// Node block: HMMA fp16 (unchanged, passing).
// ============================================================================
__global__ __launch_bounds__(256, 2) void node_kernel(
    const float* __restrict__ x,
    const float* __restrict__ bg, const float* __restrict__ bn,
    const int* __restrict__ batch, float* __restrict__ xw_out)
{
    extern __shared__ char smem[];
    const uint32_t sb = smem_u32(smem);
    const int tid = threadIdx.x, wid = tid >> 5, lane = tid & 31;
    const int wm = wid & 3, wn = wid >> 2;
    const int nBase = blockIdx.x * TILE_M;

    float* sBG = (float*)(smem + N_BG);
    float* sBN = (float*)(smem + N_BN);
    if (tid < D_HID) { sBG[tid] = bg[tid]; sBN[tid] = bn[tid]; }

    const int lo15 = lane & 15;
    const int hi   = lane >> 4;
    const int lo7  = lane & 7;
    uint32_t bXor[4];
    #pragma unroll
    for (int p = 0; p < 4; p++) bXor[p] = (uint32_t)(((wn * 8 + 2 * p + hi) ^ lo7) * 16);

    const uint32_t aBase = sb + N_A + ((16 * wm + lo15) * A_STRIDE + hi * 8) * 2;
    const uint32_t wBase = sb + N_W + lo15 * 256;

    const int rowLo = 16 * wm + (lane >> 2);
    const int rowHi = rowLo + 8;
    const int colLo = wn * 64 + (lane & 3) * 2;
    const int nLo = nBase + rowLo, nHi = nBase + rowHi;
    const int bLo = batch[min(nLo, N_NODES - 1)];
    const int bHi = batch[min(nHi, N_NODES - 1)];

    #pragma unroll
    for (int it = 0; it < 16; it++) {
        int i = tid + it * 256;
        int row = i >> 6, u = i & 63;
        int k0 = u * 4;
        int n = min(nBase + row, N_NODES - 1);
        float4 v = (k0 < D_IN)
            ? __ldg((const float4*)(x + (size_t)n * D_IN + k0))
            : *(const float4*)(g_agg + (size_t)n * D_HID + (k0 - D_IN));
        __half2 h0 = __floats2half2_rn(v.x, v.y);
        __half2 h1 = __floats2half2_rn(v.z, v.w);
        *reinterpret_cast<uint2*>(smem + N_A + (row * A_STRIDE + k0) * 2) =
            make_uint2(h2_bits(h0), h2_bits(h1));
    }
    {
        const uint4* s = (const uint4*)g_Bgh; uint4* d = (uint4*)(smem + N_W);
        #pragma unroll
        for (int i = 0; i < 16; i++) d[tid + i * 256] = s[tid + i * 256];
    }
    __syncthreads();

    float c[8][4];
    #pragma unroll
    for (int nt = 0; nt < 8; nt++)
        #pragma unroll
        for (int j = 0; j < 4; j++) c[nt][j] = 0.0f;

    #pragma unroll
    for (int ks = 0; ks < 16; ks++) {
        uint32_t a[4];
        ldm_x4(a, aBase + ks * 32);
        uint32_t bk = wBase + ks * 4096;
        #pragma unroll
        for (int p = 0; p < 4; p++) {
            uint32_t b[4];
            ldm_x4_t(b, bk + bXor[p]);
            mma16816(c[2 * p + 0], a, b[0], b[1]);
            mma16816(c[2 * p + 1], a, b[2], b[3]);
        }
    }

    float gate[8][4];
    #pragma unroll
    for (int nt = 0; nt < 8; nt++) {
        int col = nt * 8 + colLo;
        float2 bb = *(const float2*)(sBG + col);
        gate[nt][0] = 1.0f / (1.0f + __expf(-(c[nt][0] + bb.x)));
        gate[nt][1] = 1.0f / (1.0f + __expf(-(c[nt][1] + bb.y)));
        gate[nt][2] = 1.0f / (1.0f + __expf(-(c[nt][2] + bb.x)));
        gate[nt][3] = 1.0f / (1.0f + __expf(-(c[nt][3] + bb.y)));
        if (nLo < N_NODES)
            *(float2*)(xw_out + (size_t)nLo * D_HID + col) = make_float2(gate[nt][0], gate[nt][1]);
        if (nHi < N_NODES)
            *(float2*)(xw_out + (size_t)nHi * D_HID + col) = make_float2(gate[nt][2], gate[nt][3]);
    }
    if (wn == 0 && (lane & 3) == 0) {
        if (nLo < N_NODES) atomicAdd(&g_counts[bLo], 1.0f);
        if (nHi < N_NODES) atomicAdd(&g_counts[bHi], 1.0f);
    }

    __syncthreads();
    {
        const uint4* s = (const uint4*)g_Bnh; uint4* d = (uint4*)(smem + N_W);
        #pragma unroll
        for (int i = 0; i < 16; i++) d[tid + i * 256] = s[tid + i * 256];
    }
    __syncthreads();

    #pragma unroll
    for (int nt = 0; nt < 8; nt++)
        #pragma unroll
        for (int j = 0; j < 4; j++) c[nt][j] = 0.0f;

    #pragma unroll
    for (int ks = 0; ks < 16; ks++) {
        uint32_t a[4];
        ldm_x4(a, aBase + ks * 32);
        uint32_t bk = wBase + ks * 4096;
        #pragma unroll
        for (int p = 0; p < 4; p++) {
            uint32_t b[4];
            ldm_x4_t(b, bk + bXor[p]);
            mma16816(c[2 * p + 0], a, b[0], b[1]);
            mma16816(c[2 * p + 1], a, b[2], b[3]);
        }
    }

    #pragma unroll
    for (int nt = 0; nt < 8; nt++) {
        int col = nt * 8 + colLo;
        float2 bb = *(const float2*)(sBN + col);
        float x0 = gate[nt][0] * fmaxf(c[nt][0] + bb.x, 0.f);
        float x1 = gate[nt][1] * fmaxf(c[nt][1] + bb.y, 0.f);
        float x2 = gate[nt][2] * fmaxf(c[nt][2] + bb.x, 0.f);
        float x3 = gate[nt][3] * fmaxf(c[nt][3] + bb.y, 0.f);
        if (nLo < N_NODES) red_add_v2(g_pooled + (size_t)bLo * D_HID + col, x0, x1);
        if (nHi < N_NODES) red_add_v2(g_pooled + (size_t)bHi * D_HID + col, x2, x3);
    }
}

// ---------------------------------------------------------------------------
__global__ __launch_bounds__(64) void global_kernel(
    const float* __restrict__ u, const float* __restrict__ Wu,
    const float* __restrict__ bu, float* __restrict__ out)
{
    __shared__ float sin_[D_GLOB + D_HID];
    int g = blockIdx.x;
    int j = threadIdx.x;
    float cnt = fmaxf(g_counts[g], 1.0f);
    sin_[j] = u[g * D_GLOB + j];
    sin_[D_GLOB + j]      = g_pooled[g * D_HID + j] / cnt;
    sin_[D_GLOB + 64 + j] = g_pooled[g * D_HID + 64 + j] / cnt;
    __syncthreads();
    float acc = bu[j];
    #pragma unroll 8
    for (int k = 0; k < D_GLOB + D_HID; k++)
        acc = fmaf(sin_[k], Wu[k * D_GLOB + j], acc);
    out[g * D_GLOB + j] = fmaxf(acc, 0.0f);
}

// ---------------------------------------------------------------------------
extern "C" void kernel_launch(void* const* d_in, const int* in_sizes, int n_in,
                              void* d_out, int out_size)
{
    const float* x    = (const float*)d_in[0];
    const int*   eidx = (const int*)  d_in[1];
    const float* ea   = (const float*)d_in[2];
    const float* u    = (const float*)d_in[3];
    const int*   batch= (const int*)  d_in[4];
    const float* We1  = (const float*)d_in[5];
    const float* be1  = (const float*)d_in[6];
    const float* We2  = (const float*)d_in[7];
    const float* be2  = (const float*)d_in[8];
    const float* Wg   = (const float*)d_in[9];
    const float* bg   = (const float*)d_in[10];
    const float* Wn   = (const float*)d_in[11];
    const float* bn   = (const float*)d_in[12];
    const float* Wu   = (const float*)d_in[13];
    const float* bu   = (const float*)d_in[14];

    float* out   = (float*)d_out;
    float* u_new = out;
    float* xw    = out + N_GRAPHS * D_GLOB;

    cudaFuncSetAttribute(edge_kernel, cudaFuncAttributeMaxDynamicSharedMemorySize, E_TOTAL);
    cudaFuncSetAttribute(node_kernel, cudaFuncAttributeMaxDynamicSharedMemorySize, N_TOTAL);

    zero_kernel<<<2048, 256>>>();
    prep_xe<<<2048, 256>>>(x, ea);
    int prep_elems = K1 * D_HID + D_HID * D_HID + 4 * D_HID * D_HID;
    prep_w<<<(prep_elems + 255) / 256, 256>>>(We1, We2, Wg, Wn);
    edge_kernel<<<EDGE_GRID, ETHREADS, E_TOTAL>>>(eidx, be1, be2);
    node_kernel<<<(N_NODES + TILE_M - 1) / TILE_M, 256, N_TOTAL>>>(x, bg, bn, batch, xw);
    global_kernel<<<N_GRAPHS, 64>>>(u, Wu, bu, u_new);
}

// round 11
// speedup vs baseline: 1.1609x; 1.0613x over previous
#include <cuda_runtime.h>
#include <cuda_fp16.h>
#include <math.h>
#include <stdint.h>

#define N_NODES 50000
#define N_EDGES 800000
#define N_GRAPHS 512
#define D_IN 128
#define D_EDGE 32
#define D_HID 128
#define D_GLOB 64
#define K1 288

#define TILE_M 64                  /* node kernel tile */
#define TILE_E 64                  /* edge tile per warp-group */
#define NT (N_EDGES / TILE_E)      /* 12500 tiles */
#define EDGE_GRID 148
#define ETHREADS 512               /* 2 groups x 8 warps (2 wm x 4 wn, 32x32) */
#define NSTREAMS (EDGE_GRID * 2)   /* 296 tile streams */

#define A_STRIDE 296               /* halves: 592 B rows */
#define H_STRIDE 136               /* halves: 272 B rows */

// ---- scratch ----
__device__ float  g_agg[N_NODES * D_HID];
__device__ float  g_pooled[N_GRAPHS * D_HID];
__device__ float  g_counts[N_GRAPHS];
__device__ __half g_xh[N_NODES * D_IN];
__device__ __half g_eah[N_EDGES * D_EDGE];
// fp16 weight images: byte(k,n) = k*256 + (((n>>3)^(k&7))*16) + (n&7)*2
__device__ __half g_B1h[K1 * D_HID];
__device__ __half g_B2h[D_HID * D_HID];
__device__ __half g_Bgh[2 * D_HID * D_HID];
__device__ __half g_Bnh[2 * D_HID * D_HID];

// ---- edge kernel SMEM layout (bytes) ----
// idx per group: 2 bufs x (64 src + 64 dst) ints; group g at +g*1024, buf pb at +pb*512
#define E_IDX   0                          /* 2048 */
#define E_BE1   2048
#define E_BE2   2560
#define E_A     3072                       /* 2 groups x 64 x 592 = 75776 */
#define E_H     (E_A + 75776)              /* 78848: 2 groups x 64 x 272 = 34816 */
#define E_W1    (E_H + 34816)              /* 113664: 73728 */
#define E_W2    (E_W1 + 73728)             /* 187392: 32768 */
#define E_TOTAL (E_W2 + 32768)             /* 220160 */

#define A_GRP 37888
#define H_GRP 17408

// ---- node kernel SMEM layout ----
#define N_BG    0
#define N_BN    512
#define N_A     1024
#define N_W     (N_A + 37888)
#define N_TOTAL (N_W + 65536)

// ============================ PTX helpers ===================================
__device__ __forceinline__ uint32_t smem_u32(const void* p) {
    uint32_t a;
    asm("{ .reg .u64 t; cvta.to.shared.u64 t, %1; cvt.u32.u64 %0, t; }" : "=r"(a) : "l"(p));
    return a;
}
__device__ __forceinline__ void barg(int id) {
    asm volatile("bar.sync %0, %1;" :: "r"(id), "r"(256) : "memory");
}
__device__ __forceinline__ void ldm_x4(uint32_t* r, uint32_t addr) {
    asm volatile("ldmatrix.sync.aligned.m8n8.x4.shared.b16 {%0,%1,%2,%3}, [%4];"
                 : "=r"(r[0]), "=r"(r[1]), "=r"(r[2]), "=r"(r[3]) : "r"(addr));
}
__device__ __forceinline__ void ldm_x4_t(uint32_t* r, uint32_t addr) {
    asm volatile("ldmatrix.sync.aligned.m8n8.x4.trans.shared.b16 {%0,%1,%2,%3}, [%4];"
                 : "=r"(r[0]), "=r"(r[1]), "=r"(r[2]), "=r"(r[3]) : "r"(addr));
}
__device__ __forceinline__ void mma16816(float* c, const uint32_t* a, uint32_t b0, uint32_t b1) {
    asm volatile(
        "mma.sync.aligned.m16n8k16.row.col.f32.f16.f16.f32 "
        "{%0,%1,%2,%3}, {%4,%5,%6,%7}, {%8,%9}, {%0,%1,%2,%3};"
        : "+f"(c[0]), "+f"(c[1]), "+f"(c[2]), "+f"(c[3])
        : "r"(a[0]), "r"(a[1]), "r"(a[2]), "r"(a[3]), "r"(b0), "r"(b1));
}
__device__ __forceinline__ void red_add_v4(float* p, float a, float b, float c, float d) {
    asm volatile("red.global.add.v4.f32 [%0], {%1, %2, %3, %4};"
                 :: "l"(p), "f"(a), "f"(b), "f"(c), "f"(d) : "memory");
}
__device__ __forceinline__ void red_add_v2(float* p, float a, float b) {
    asm volatile("red.global.add.v2.f32 [%0], {%1, %2};" :: "l"(p), "f"(a), "f"(b) : "memory");
}
__device__ __forceinline__ void cpa16(uint32_t dst, const void* src) {
    asm volatile("cp.async.cg.shared.global [%0], [%1], 16;" :: "r"(dst), "l"(src) : "memory");
}
#define CPA_COMMIT() asm volatile("cp.async.commit_group;" ::: "memory")
#define CPA_WAIT0()  asm volatile("cp.async.wait_group 0;" ::: "memory")
__device__ __forceinline__ uint32_t h2_bits(__half2 h) {
    return *reinterpret_cast<uint32_t*>(&h);
}

// ============================================================================
// Fused prep: zero scratch + fp16-convert x/ea + build weight images.
// ============================================================================
__global__ void prep_all(const float* __restrict__ x, const float* __restrict__ ea,
                         const float* __restrict__ We1, const float* __restrict__ We2,
                         const float* __restrict__ Wg,  const float* __restrict__ Wn) {
    int idx = blockIdx.x * blockDim.x + threadIdx.x;
    int stride = gridDim.x * blockDim.x;
    float4 z = make_float4(0.f, 0.f, 0.f, 0.f);
    float4* a4 = (float4*)g_agg;
    for (int i = idx; i < N_NODES * D_HID / 4; i += stride) a4[i] = z;
    for (int i = idx; i < N_GRAPHS * D_HID; i += stride) g_pooled[i] = 0.0f;
    for (int i = idx; i < N_GRAPHS; i += stride) g_counts[i] = 0.0f;

    const int NX = N_NODES * D_IN / 4, NE = N_EDGES * D_EDGE / 4;
    for (int i = idx; i < NX; i += stride) {
        float4 v = __ldg((const float4*)x + i);
        __half2 h0 = __floats2half2_rn(v.x, v.y), h1 = __floats2half2_rn(v.z, v.w);
        *((uint2*)g_xh + i) = make_uint2(h2_bits(h0), h2_bits(h1));
    }
    for (int i = idx; i < NE; i += stride) {
        float4 v = __ldg((const float4*)ea + i);
        __half2 h0 = __floats2half2_rn(v.x, v.y), h1 = __floats2half2_rn(v.z, v.w);
        *((uint2*)g_eah + i) = make_uint2(h2_bits(h0), h2_bits(h1));
    }
    // weight images
    for (int i = idx; i < K1 * D_HID; i += stride) {
        int k = i >> 7, n = i & 127;
        uint32_t off = (uint32_t)k * 256 + (((n >> 3) ^ (k & 7)) * 16) + (n & 7) * 2;
        *(__half*)((char*)g_B1h + off) = __float2half_rn(We1[k * D_HID + n]);
    }
    for (int i = idx; i < D_HID * D_HID; i += stride) {
        int k = i >> 7, n = i & 127;
        uint32_t off = (uint32_t)k * 256 + (((n >> 3) ^ (k & 7)) * 16) + (n & 7) * 2;
        *(__half*)((char*)g_B2h + off) = __float2half_rn(We2[k * D_HID + n]);
    }
    for (int i = idx; i < 2 * D_HID * D_HID; i += stride) {
        int k = i >> 7, n = i & 127;
        uint32_t off = (uint32_t)k * 256 + (((n >> 3) ^ (k & 7)) * 16) + (n & 7) * 2;
        *(__half*)((char*)g_Bgh + off) = __float2half_rn(Wg[k * D_HID + n]);
        *(__half*)((char*)g_Bnh + off) = __float2half_rn(Wn[k * D_HID + n]);
    }
}

// ============================================================================
// Edge block: persistent CTAs, TWO independent 8-warp groups per CTA, each
// streaming its own 64-edge tiles (named barriers); shared resident weights;
// overlapped cp.async gather; shuffle + direct v4 scatter.
// Group warp grid: wm in {0,1} (32-row slabs), wn in {0..3} (32-col).
// ============================================================================
__global__ __launch_bounds__(ETHREADS, 1) void edge_kernel(
    const int* __restrict__ eidx,
    const float* __restrict__ be1, const float* __restrict__ be2)
{
    extern __shared__ char smem[];
    const uint32_t sb = smem_u32(smem);
    const int tid = threadIdx.x, wid = tid >> 5, lane = tid & 31;
    const int grp = tid >> 8;                 // warp-group 0/1
    const int lwid = wid & 7;                 // warp within group
    const int ltid = tid & 255;
    const int wm = lwid & 1, wn = lwid >> 1;
    const int barid = grp + 1;

    int*   sIdx = (int*)(smem + E_IDX + grp * 1024);  // buf pb at +pb*128 ints
    float* sBE1 = (float*)(smem + E_BE1);
    float* sBE2 = (float*)(smem + E_BE2);

    if (tid < D_HID) { sBE1[tid] = be1[tid]; sBE2[tid] = be2[tid]; }

    // resident weights (whole CTA cooperates), then one full barrier
    {
        const uint4* s1 = (const uint4*)g_B1h; uint4* d1 = (uint4*)(smem + E_W1);
        #pragma unroll
        for (int i = 0; i < 9; i++) d1[tid + i * 512] = s1[tid + i * 512];
        const uint4* s2 = (const uint4*)g_B2h; uint4* d2 = (uint4*)(smem + E_W2);
        #pragma unroll
        for (int i = 0; i < 4; i++) d2[tid + i * 512] = s2[tid + i * 512];
    }
    __syncthreads();   // LAST full-CTA barrier; groups diverge after this

    const int lo15 = lane & 15;
    const int hi   = lane >> 4;
    const int lo7  = lane & 7;
    uint32_t bXor[2];
    #pragma unroll
    for (int p = 0; p < 2; p++) bXor[p] = (uint32_t)(((wn * 4 + 2 * p + hi) ^ lo7) * 16);

    const uint32_t aG = sb + E_A + grp * A_GRP;
    const uint32_t hG = sb + E_H + grp * H_GRP;
    const uint32_t aBase0 = aG + ((32 * wm + lo15) * A_STRIDE + hi * 8) * 2;
    const uint32_t aBase1 = aBase0 + 16 * A_STRIDE * 2;
    const uint32_t hBase0 = hG + ((32 * wm + lo15) * H_STRIDE + hi * 8) * 2;
    const uint32_t hBase1 = hBase0 + 16 * H_STRIDE * 2;
    const uint32_t w1Base = sb + E_W1 + lo15 * 256;
    const uint32_t w2Base = sb + E_W2 + lo15 * 256;

    const int rowLo = 32 * wm + (lane >> 2);
    const int colLo = wn * 32 + (lane & 3) * 2;
    const int odd   = lane & 1;
    const int col4  = wn * 32 + ((lane & 3) >> 1) * 4;

    int t = blockIdx.x * 2 + grp;
    int pb = 0;
    // prologue: idx(t) into buf 0
    if (ltid < TILE_E)            sIdx[ltid] = eidx[t * TILE_E + ltid];
    else if (ltid < 2 * TILE_E)   sIdx[ltid] = eidx[N_EDGES + t * TILE_E + (ltid - TILE_E)];
    barg(barid);
    // gather(t): 64 rows x 36 units = 2304 cp.async over 256 threads
    {
        const int* sS = sIdx, *sD = sIdx + TILE_E;
        #pragma unroll
        for (int it = 0; it < 9; it++) {
            int i = ltid + it * 256;
            int row = i / 36, u = i - row * 36;
            const void* src;
            if (u < 16)      src = g_xh + (size_t)sS[row] * D_IN + u * 8;
            else if (u < 32) src = g_xh + (size_t)sD[row] * D_IN + (u - 16) * 8;
            else             src = g_eah + (size_t)(t * TILE_E + row) * D_EDGE + (u - 32) * 8;
            cpa16(aG + row * 592 + u * 16, src);
        }
        CPA_COMMIT();
    }

    for (; t < NT; t += NSTREAMS, pb ^= 1) {
        const int tn = t + NSTREAMS;
        if (tn < NT) {
            if (ltid < TILE_E)          sIdx[(pb ^ 1) * 128 + ltid] = eidx[tn * TILE_E + ltid];
            else if (ltid < 2 * TILE_E) sIdx[(pb ^ 1) * 128 + ltid] =
                                            eidx[N_EDGES + tn * TILE_E + (ltid - TILE_E)];
        }
        CPA_WAIT0();
        barg(barid);   // A(t) ready; idx(tn) visible; prior H reads done

        float c[2][4][4];
        #pragma unroll
        for (int mi = 0; mi < 2; mi++)
            #pragma unroll
            for (int nt = 0; nt < 4; nt++)
                #pragma unroll
                for (int j = 0; j < 4; j++) c[mi][nt][j] = 0.0f;

        // ---- layer 1: K = 288 ----
        #pragma unroll
        for (int ks = 0; ks < 18; ks++) {
            uint32_t a0[4], a1[4];
            ldm_x4(a0, aBase0 + ks * 32);
            ldm_x4(a1, aBase1 + ks * 32);
            uint32_t bk = w1Base + ks * 4096;
            #pragma unroll
            for (int p = 0; p < 2; p++) {
                uint32_t b[4];
                ldm_x4_t(b, bk + bXor[p]);
                mma16816(c[0][2 * p + 0], a0, b[0], b[1]);
                mma16816(c[0][2 * p + 1], a0, b[2], b[3]);
                mma16816(c[1][2 * p + 0], a1, b[0], b[1]);
                mma16816(c[1][2 * p + 1], a1, b[2], b[3]);
            }
        }
        barg(barid);   // all layer-1 A reads done -> A free

        // issue gather(tn) into A (overlaps epilogue1 + layer2 + scatter)
        if (tn < NT) {
            const int* sS = sIdx + (pb ^ 1) * 128, *sD = sS + TILE_E;
            #pragma unroll
            for (int it = 0; it < 9; it++) {
                int i = ltid + it * 256;
                int row = i / 36, u = i - row * 36;
                const void* src;
                if (u < 16)      src = g_xh + (size_t)sS[row] * D_IN + u * 8;
                else if (u < 32) src = g_xh + (size_t)sD[row] * D_IN + (u - 16) * 8;
                else             src = g_eah + (size_t)(tn * TILE_E + row) * D_EDGE + (u - 32) * 8;
                cpa16(aG + row * 592 + u * 16, src);
            }
            CPA_COMMIT();
        }

        // epilogue 1: bias+relu -> fp16 H
        #pragma unroll
        for (int mi = 0; mi < 2; mi++) {
            int r0 = rowLo + 16 * mi;
            #pragma unroll
            for (int nt = 0; nt < 4; nt++) {
                int col = nt * 8 + colLo;
                float2 bb = *(const float2*)(sBE1 + col);
                float v0 = fmaxf(c[mi][nt][0] + bb.x, 0.f);
                float v1 = fmaxf(c[mi][nt][1] + bb.y, 0.f);
                float v2 = fmaxf(c[mi][nt][2] + bb.x, 0.f);
                float v3 = fmaxf(c[mi][nt][3] + bb.y, 0.f);
                *(uint32_t*)(smem + (hG - sb) + (r0 * H_STRIDE + col) * 2) =
                    h2_bits(__floats2half2_rn(v0, v1));
                *(uint32_t*)(smem + (hG - sb) + ((r0 + 8) * H_STRIDE + col) * 2) =
                    h2_bits(__floats2half2_rn(v2, v3));
            }
        }
        barg(barid);   // H visible

        #pragma unroll
        for (int mi = 0; mi < 2; mi++)
            #pragma unroll
            for (int nt = 0; nt < 4; nt++)
                #pragma unroll
                for (int j = 0; j < 4; j++) c[mi][nt][j] = 0.0f;

        // ---- layer 2: K = 128 ----
        #pragma unroll
        for (int ks = 0; ks < 8; ks++) {
            uint32_t a0[4], a1[4];
            ldm_x4(a0, hBase0 + ks * 32);
            ldm_x4(a1, hBase1 + ks * 32);
            uint32_t bk = w2Base + ks * 4096;
            #pragma unroll
            for (int p = 0; p < 2; p++) {
                uint32_t b[4];
                ldm_x4_t(b, bk + bXor[p]);
                mma16816(c[0][2 * p + 0], a0, b[0], b[1]);
                mma16816(c[0][2 * p + 1], a0, b[2], b[3]);
                mma16816(c[1][2 * p + 0], a1, b[0], b[1]);
                mma16816(c[1][2 * p + 1], a1, b[2], b[3]);
            }
        }

        // epilogue 2: bias+relu, pair-shuffle -> direct red.global.add.v4
        const int* sDstP = sIdx + pb * 128 + TILE_E;
        #pragma unroll
        for (int mi = 0; mi < 2; mi++) {
            int rT = rowLo + 16 * mi;
            int rB = rT + 8;
            float* dp = g_agg + (size_t)sDstP[odd ? rB : rT] * D_HID;
            #pragma unroll
            for (int nt = 0; nt < 4; nt++) {
                int col = nt * 8 + colLo;
                float2 bb = *(const float2*)(sBE2 + col);
                float t0 = fmaxf(c[mi][nt][0] + bb.x, 0.f);
                float t1 = fmaxf(c[mi][nt][1] + bb.y, 0.f);
                float b0 = fmaxf(c[mi][nt][2] + bb.x, 0.f);
                float b1 = fmaxf(c[mi][nt][3] + bb.y, 0.f);
                float2 send = odd ? make_float2(t0, t1) : make_float2(b0, b1);
                unsigned long long sv = *reinterpret_cast<unsigned long long*>(&send);
                unsigned long long rvu = __shfl_xor_sync(0xffffffffu, sv, 1);
                float2 rv = *reinterpret_cast<float2*>(&rvu);
                if (!odd) red_add_v4(dp + nt * 8 + col4, t0, t1, rv.x, rv.y);
                else      red_add_v4(dp + nt * 8 + col4, rv.x, rv.y, b0, b1);
            }
        }
        // no trailing barrier: loop-top barg orders scatter/H reuse vs next tile
    }
}

// ============================================================================
// Node block: HMMA fp16 (unchanged, passing).
// ============================================================================
__global__ __launch_bounds__(256, 2) void node_kernel(
    const float* __restrict__ x,
    const float* __restrict__ bg, const float* __restrict__ bn,
    const int* __restrict__ batch, float* __restrict__ xw_out)
{
    extern __shared__ char smem[];
    const uint32_t sb = smem_u32(smem);
    const int tid = threadIdx.x, wid = tid >> 5, lane = tid & 31;
    const int wm = wid & 3, wn = wid >> 2;
    const int nBase = blockIdx.x * TILE_M;

    float* sBG = (float*)(smem + N_BG);
    float* sBN = (float*)(smem + N_BN);
    if (tid < D_HID) { sBG[tid] = bg[tid]; sBN[tid] = bn[tid]; }

    const int lo15 = lane & 15;
    const int hi   = lane >> 4;
    const int lo7  = lane & 7;
    uint32_t bXor[4];
    #pragma unroll
    for (int p = 0; p < 4; p++) bXor[p] = (uint32_t)(((wn * 8 + 2 * p + hi) ^ lo7) * 16);

    const uint32_t aBase = sb + N_A + ((16 * wm + lo15) * A_STRIDE + hi * 8) * 2;
    const uint32_t wBase = sb + N_W + lo15 * 256;

    const int rowLo = 16 * wm + (lane >> 2);
    const int rowHi = rowLo + 8;
    const int colLo = wn * 64 + (lane & 3) * 2;
    const int nLo = nBase + rowLo, nHi = nBase + rowHi;
    const int bLo = batch[min(nLo, N_NODES - 1)];
    const int bHi = batch[min(nHi, N_NODES - 1)];

    #pragma unroll
    for (int it = 0; it < 16; it++) {
        int i = tid + it * 256;
        int row = i >> 6, u = i & 63;
        int k0 = u * 4;
        int n = min(nBase + row, N_NODES - 1);
        float4 v = (k0 < D_IN)
            ? __ldg((const float4*)(x + (size_t)n * D_IN + k0))
            : *(const float4*)(g_agg + (size_t)n * D_HID + (k0 - D_IN));
        __half2 h0 = __floats2half2_rn(v.x, v.y);
        __half2 h1 = __floats2half2_rn(v.z, v.w);
        *reinterpret_cast<uint2*>(smem + N_A + (row * A_STRIDE + k0) * 2) =
            make_uint2(h2_bits(h0), h2_bits(h1));
    }
    {
        const uint4* s = (const uint4*)g_Bgh; uint4* d = (uint4*)(smem + N_W);
        #pragma unroll
        for (int i = 0; i < 16; i++) d[tid + i * 256] = s[tid + i * 256];
    }
    __syncthreads();

    float c[8][4];
    #pragma unroll
    for (int nt = 0; nt < 8; nt++)
        #pragma unroll
        for (int j = 0; j < 4; j++) c[nt][j] = 0.0f;

    #pragma unroll
    for (int ks = 0; ks < 16; ks++) {
        uint32_t a[4];
        ldm_x4(a, aBase + ks * 32);
        uint32_t bk = wBase + ks * 4096;
        #pragma unroll
        for (int p = 0; p < 4; p++) {
            uint32_t b[4];
            ldm_x4_t(b, bk + bXor[p]);
            mma16816(c[2 * p + 0], a, b[0], b[1]);
            mma16816(c[2 * p + 1], a, b[2], b[3]);
        }
    }

    float gate[8][4];
    #pragma unroll
    for (int nt = 0; nt < 8; nt++) {
        int col = nt * 8 + colLo;
        float2 bb = *(const float2*)(sBG + col);
        gate[nt][0] = 1.0f / (1.0f + __expf(-(c[nt][0] + bb.x)));
        gate[nt][1] = 1.0f / (1.0f + __expf(-(c[nt][1] + bb.y)));
        gate[nt][2] = 1.0f / (1.0f + __expf(-(c[nt][2] + bb.x)));
        gate[nt][3] = 1.0f / (1.0f + __expf(-(c[nt][3] + bb.y)));
        if (nLo < N_NODES)
            *(float2*)(xw_out + (size_t)nLo * D_HID + col) = make_float2(gate[nt][0], gate[nt][1]);
        if (nHi < N_NODES)
            *(float2*)(xw_out + (size_t)nHi * D_HID + col) = make_float2(gate[nt][2], gate[nt][3]);
    }
    if (wn == 0 && (lane & 3) == 0) {
        if (nLo < N_NODES) atomicAdd(&g_counts[bLo], 1.0f);
        if (nHi < N_NODES) atomicAdd(&g_counts[bHi], 1.0f);
    }

    __syncthreads();
    {
        const uint4* s = (const uint4*)g_Bnh; uint4* d = (uint4*)(smem + N_W);
        #pragma unroll
        for (int i = 0; i < 16; i++) d[tid + i * 256] = s[tid + i * 256];
    }
    __syncthreads();

    #pragma unroll
    for (int nt = 0; nt < 8; nt++)
        #pragma unroll
        for (int j = 0; j < 4; j++) c[nt][j] = 0.0f;

    #pragma unroll
    for (int ks = 0; ks < 16; ks++) {
        uint32_t a[4];
        ldm_x4(a, aBase + ks * 32);
        uint32_t bk = wBase + ks * 4096;
        #pragma unroll
        for (int p = 0; p < 4; p++) {
            uint32_t b[4];
            ldm_x4_t(b, bk + bXor[p]);
            mma16816(c[2 * p + 0], a, b[0], b[1]);
            mma16816(c[2 * p + 1], a, b[2], b[3]);
        }
    }

    #pragma unroll
    for (int nt = 0; nt < 8; nt++) {
        int col = nt * 8 + colLo;
        float2 bb = *(const float2*)(sBN + col);
        float x0 = gate[nt][0] * fmaxf(c[nt][0] + bb.x, 0.f);
        float x1 = gate[nt][1] * fmaxf(c[nt][1] + bb.y, 0.f);
        float x2 = gate[nt][2] * fmaxf(c[nt][2] + bb.x, 0.f);
        float x3 = gate[nt][3] * fmaxf(c[nt][3] + bb.y, 0.f);
        if (nLo < N_NODES) red_add_v2(g_pooled + (size_t)bLo * D_HID + col, x0, x1);
        if (nHi < N_NODES) red_add_v2(g_pooled + (size_t)bHi * D_HID + col, x2, x3);
    }
}

// ---------------------------------------------------------------------------
__global__ __launch_bounds__(64) void global_kernel(
    const float* __restrict__ u, const float* __restrict__ Wu,
    const float* __restrict__ bu, float* __restrict__ out)
{
    __shared__ float sin_[D_GLOB + D_HID];
    int g = blockIdx.x;
    int j = threadIdx.x;
    float cnt = fmaxf(g_counts[g], 1.0f);
    sin_[j] = u[g * D_GLOB + j];
    sin_[D_GLOB + j]      = g_pooled[g * D_HID + j] / cnt;
    sin_[D_GLOB + 64 + j] = g_pooled[g * D_HID + 64 + j] / cnt;
    __syncthreads();
    float acc = bu[j];
    #pragma unroll 8
    for (int k = 0; k < D_GLOB + D_HID; k++)
        acc = fmaf(sin_[k], Wu[k * D_GLOB + j], acc);
    out[g * D_GLOB + j] = fmaxf(acc, 0.0f);
}

// ---------------------------------------------------------------------------
extern "C" void kernel_launch(void* const* d_in, const int* in_sizes, int n_in,
                              void* d_out, int out_size)
{
    const float* x    = (const float*)d_in[0];
    const int*   eidx = (const int*)  d_in[1];
    const float* ea   = (const float*)d_in[2];
    const float* u    = (const float*)d_in[3];
    const int*   batch= (const int*)  d_in[4];
    const float* We1  = (const float*)d_in[5];
    const float* be1  = (const float*)d_in[6];
    const float* We2  = (const float*)d_in[7];
    const float* be2  = (const float*)d_in[8];
    const float* Wg   = (const float*)d_in[9];
    const float* bg   = (const float*)d_in[10];
    const float* Wn   = (const float*)d_in[11];
    const float* bn   = (const float*)d_in[12];
    const float* Wu   = (const float*)d_in[13];
    const float* bu   = (const float*)d_in[14];

    float* out   = (float*)d_out;
    float* u_new = out;
    float* xw    = out + N_GRAPHS * D_GLOB;

    cudaFuncSetAttribute(edge_kernel, cudaFuncAttributeMaxDynamicSharedMemorySize, E_TOTAL);
    cudaFuncSetAttribute(node_kernel, cudaFuncAttributeMaxDynamicSharedMemorySize, N_TOTAL);

    prep_all<<<2048, 256>>>(x, ea, We1, We2, Wg, Wn);
    edge_kernel<<<EDGE_GRID, ETHREADS, E_TOTAL>>>(eidx, be1, be2);
    node_kernel<<<(N_NODES + TILE_M - 1) / TILE_M, 256, N_TOTAL>>>(x, bg, bn, batch, xw);
    global_kernel<<<N_GRAPHS, 64>>>(u, Wu, bu, u_new);
}